// round 3
// baseline (speedup 1.0000x reference)
#include <cuda_runtime.h>
#include <cuda_bf16.h>

// MultiBoxLoss (SSD): per-anchor CE + smooth-L1 on positives + hard negative
// mining (top 3*num_pos CE among negatives per row), reduced to one scalar.
//
// Shapes: confidences (128, 8732, 21) f32, locations (128, 8732, 4) f32,
//         gt_labels (128, 8732) i32, gt_locations (128, 8732, 4) f32.
// Output: 1 float.

#define BB 128
#define AA 8732
#define CC 21
#define NT 1024
#define PER 9  // ceil(8732/1024)

__device__ double g_sum;               // loc_loss + conf_loss accumulator
__device__ unsigned long long g_npos;  // total positive count

__global__ void mbl_zero_kernel() {
    g_sum = 0.0;
    g_npos = 0ull;
}

__global__ __launch_bounds__(NT) void mbl_main_kernel(
    const float* __restrict__ conf,
    const float* __restrict__ loc,
    const int*   __restrict__ lab,
    const float* __restrict__ gloc)
{
    const int b   = blockIdx.x;
    const int tid = threadIdx.x;
    const unsigned lane = tid & 31u;

    __shared__ unsigned s_cnt[34];   // one slot per bisection iteration
    __shared__ float    s_fsum;      // sum of ce strictly above threshold
    __shared__ unsigned s_cgt;       // count strictly above threshold
    __shared__ double   s_loc, s_posce;
    __shared__ int      s_poscnt, s_negcnt;

    if (tid < 34) s_cnt[tid] = 0u;
    if (tid == 0) {
        s_fsum = 0.f; s_cgt = 0u;
        s_loc = 0.0; s_posce = 0.0;
        s_poscnt = 0; s_negcnt = 0;
    }
    __syncthreads();

    // ---------------- Phase A: per-anchor CE, smooth-L1, counts ----------------
    float ce_reg[PER];
    float loc_acc = 0.f, posce = 0.f;
    int   poscnt = 0, negcnt = 0;
    const size_t rowbase = (size_t)b * AA;

    #pragma unroll
    for (int i = 0; i < PER; i++) {
        const int a = tid + i * NT;
        float cev = 0.f;  // ce_neg (0 for positives / out-of-range)
        if (a < AA) {
            const size_t idx = rowbase + (size_t)a;
            const float* cf = conf + idx * CC;
            float v[CC];
            #pragma unroll
            for (int c = 0; c < CC; c++) v[c] = __ldg(cf + c);

            float m = v[0];
            #pragma unroll
            for (int c = 1; c < CC; c++) m = fmaxf(m, v[c]);
            float s = 0.f;
            #pragma unroll
            for (int c = 0; c < CC; c++) s += __expf(v[c] - m);

            const int lb = lab[idx];
            const float ce = m + __logf(s) - v[lb];

            if (lb > 0) {
                poscnt++;
                posce += ce;
                #pragma unroll
                for (int j = 0; j < 4; j++) {
                    const float d  = loc[idx * 4 + j] - gloc[idx * 4 + j];
                    const float ad = fabsf(d);
                    loc_acc += (ad < 1.f) ? 0.5f * d * d : ad - 0.5f;
                }
            } else {
                negcnt++;
                cev = ce;  // CE > 0 strictly for any finite logits
            }
        }
        ce_reg[i] = cev;
    }

    // Block reduce scalar stats (warp shuffle -> smem atomics).
    #pragma unroll
    for (int off = 16; off; off >>= 1) {
        poscnt  += __shfl_down_sync(0xFFFFFFFFu, poscnt,  off);
        negcnt  += __shfl_down_sync(0xFFFFFFFFu, negcnt,  off);
        posce   += __shfl_down_sync(0xFFFFFFFFu, posce,   off);
        loc_acc += __shfl_down_sync(0xFFFFFFFFu, loc_acc, off);
    }
    if (lane == 0) {
        atomicAdd(&s_poscnt, poscnt);
        atomicAdd(&s_negcnt, negcnt);
        atomicAdd(&s_posce, (double)posce);
        atomicAdd(&s_loc,   (double)loc_acc);
    }
    __syncthreads();

    const int k = min(3 * s_poscnt, s_negcnt);  // num_neg for this row

    // ---------------- Phase B: bisection on float bits for k-th largest ----------------
    // All ce_neg >= 0 so the IEEE bit pattern is monotone as an unsigned int.
    double negsum = 0.0;
    if (k > 0) {
        unsigned bits[PER];
        #pragma unroll
        for (int i = 0; i < PER; i++) bits[i] = __float_as_uint(ce_reg[i]);

        unsigned lo = 0u, hi = 0x7F800000u;  // [0, +inf)
        int iter = 0;
        while (lo < hi) {
            const unsigned mid = (lo + hi) >> 1;
            unsigned c = 0;
            #pragma unroll
            for (int i = 0; i < PER; i++) c += (bits[i] > mid) ? 1u : 0u;
            #pragma unroll
            for (int off = 16; off; off >>= 1)
                c += __shfl_down_sync(0xFFFFFFFFu, c, off);
            if (lane == 0) atomicAdd(&s_cnt[iter], c);
            __syncthreads();
            const unsigned tot = s_cnt[iter];  // identical in all threads
            if (tot < (unsigned)k) hi = mid; else lo = mid + 1u;
            iter++;
        }
        // lo = minimal t with count(bits > t) < k  =>  val(lo) is the k-th largest.
        const unsigned vbits = lo;
        const float    vth   = __uint_as_float(vbits);

        float    fs  = 0.f;
        unsigned cgt = 0u;
        #pragma unroll
        for (int i = 0; i < PER; i++) {
            if (bits[i] > vbits) { fs += ce_reg[i]; cgt++; }
        }
        #pragma unroll
        for (int off = 16; off; off >>= 1) {
            fs  += __shfl_down_sync(0xFFFFFFFFu, fs,  off);
            cgt += __shfl_down_sync(0xFFFFFFFFu, cgt, off);
        }
        if (lane == 0) {
            atomicAdd(&s_fsum, fs);
            atomicAdd(&s_cgt,  cgt);
        }
        __syncthreads();
        negsum = (double)s_fsum + (double)(k - (int)s_cgt) * (double)vth;
    }

    if (tid == 0) {
        const double row_total = s_loc + s_posce + negsum;
        atomicAdd(&g_sum, row_total);
        atomicAdd(&g_npos, (unsigned long long)s_poscnt);
    }
}

__global__ void mbl_fin_kernel(float* __restrict__ out) {
    out[0] = (float)(g_sum / (double)g_npos);
}

extern "C" void kernel_launch(void* const* d_in, const int* in_sizes, int n_in,
                              void* d_out, int out_size)
{
    const float* conf = (const float*)d_in[0];
    const float* loc  = (const float*)d_in[1];
    const int*   lab  = (const int*)  d_in[2];
    const float* gloc = (const float*)d_in[3];
    float* out = (float*)d_out;

    mbl_zero_kernel<<<1, 1>>>();
    mbl_main_kernel<<<BB, NT>>>(conf, loc, lab, gloc);
    mbl_fin_kernel<<<1, 1>>>(out);
}

// round 4
// speedup vs baseline: 1.6806x; 1.6806x over previous
#include <cuda_runtime.h>
#include <cuda_bf16.h>

// MultiBoxLoss (SSD). 3-kernel pipeline, no global atomics, no zero kernel:
//  A) stream: per-anchor CE -> g_ce scratch; per-chunk (32 anchors) positive
//     count + (posCE + smoothL1) partial sums. Coalesced float4 smem staging.
//  B) per-row: reduce chunk partials -> k = min(3*npos, nneg); exact top-k CE
//     sum via bisection on float bit patterns (ce_neg >= 0 -> uint-monotone).
//  C) finalize: reduce 128 row results, divide by total npos.

#define ROWS 128
#define AA   8732
#define CC   21
#define CPR  273            // chunks per row: 272 full (32) + 1 partial (28)
#define TOTCH (ROWS * CPR)  // 34944
#define WPB  8              // warps per block in phase A
#define BLKA (TOTCH / WPB)  // 4368
#define NTB  1024
#define PER  9              // ceil(8732/1024)

__device__ float  g_ce[ROWS * AA];      // ce_neg (0 for positives)
__device__ int    g_chunk_pos[TOTCH];
__device__ float  g_chunk_sum[TOTCH];   // posCE + smoothL1 partial per chunk
__device__ double g_rowsum[ROWS];
__device__ int    g_rowpos[ROWS];

// ---------------------------------------------------------------- Phase A
__global__ __launch_bounds__(256) void mbl_phaseA(
    const float* __restrict__ conf,
    const float* __restrict__ loc,
    const int*   __restrict__ lab,
    const float* __restrict__ gloc)
{
    __shared__ float sbuf[WPB * 672];   // 21504 B

    const int wid  = threadIdx.x >> 5;
    const int lane = threadIdx.x & 31;
    const int chunk = blockIdx.x * WPB + wid;
    const int row = chunk / CPR;
    const int j   = chunk - row * CPR;
    const int na  = (j == CPR - 1) ? (AA - (CPR - 1) * 32) : 32;  // 28 or 32
    const size_t abase = (size_t)row * AA + (size_t)j * 32;

    // Stage this chunk's logits: na*21 floats, contiguous & 16B-aligned.
    float* sw = sbuf + wid * 672;
    const float4* src = (const float4*)(conf + abase * CC);
    const int n4 = (na * CC) >> 2;  // 168 or 147
    for (int t = lane; t < n4; t += 32)
        ((float4*)sw)[t] = src[t];
    __syncwarp();

    float cev = 0.f;    // ce_neg
    int   isp = 0;
    float psum = 0.f;   // posCE + smoothL1 contribution
    if (lane < na) {
        float v[CC];
        #pragma unroll
        for (int c = 0; c < CC; c++) v[c] = sw[lane * CC + c];

        float m = v[0];
        #pragma unroll
        for (int c = 1; c < CC; c++) m = fmaxf(m, v[c]);
        float s = 0.f;
        #pragma unroll
        for (int c = 0; c < CC; c++) s += __expf(v[c] - m);

        const size_t idx = abase + (size_t)lane;
        const int lb = lab[idx];
        const float ce = m + __logf(s) - v[lb];

        if (lb > 0) {
            isp = 1;
            psum = ce;
            #pragma unroll
            for (int q = 0; q < 4; q++) {
                const float d  = loc[idx * 4 + q] - gloc[idx * 4 + q];
                const float ad = fabsf(d);
                psum += (ad < 1.f) ? 0.5f * d * d : ad - 0.5f;
            }
        } else {
            cev = ce;   // strictly > 0 for finite logits
        }
        g_ce[idx] = cev;
    }

    // Warp-level chunk partials
    int pc = (int)__reduce_add_sync(0xFFFFFFFFu, (unsigned)isp);
    #pragma unroll
    for (int off = 16; off; off >>= 1)
        psum += __shfl_xor_sync(0xFFFFFFFFu, psum, off);
    if (lane == 0) {
        g_chunk_pos[chunk] = pc;
        g_chunk_sum[chunk] = psum;
    }
}

// ---------------------------------------------------------------- Phase B
__global__ __launch_bounds__(NTB) void mbl_phaseB()
{
    const int b    = blockIdx.x;
    const int tid  = threadIdx.x;
    const unsigned lane = tid & 31u;

    __shared__ unsigned s_cnt[40];
    __shared__ float    s_fsum;
    __shared__ unsigned s_cgt;
    __shared__ int      s_pos;
    __shared__ double   s_psum;

    if (tid < 40) s_cnt[tid] = 0u;
    if (tid == 0) { s_fsum = 0.f; s_cgt = 0u; s_pos = 0; s_psum = 0.0; }
    __syncthreads();

    // Reduce this row's chunk partials (273 of them).
    {
        int   pc = 0;
        float ps = 0.f;
        if (tid < CPR) {
            pc = g_chunk_pos[b * CPR + tid];
            ps = g_chunk_sum[b * CPR + tid];
        }
        pc = (int)__reduce_add_sync(0xFFFFFFFFu, (unsigned)pc);
        #pragma unroll
        for (int off = 16; off; off >>= 1)
            ps += __shfl_down_sync(0xFFFFFFFFu, ps, off);
        if (lane == 0 && pc + ps != 0.f) { }   // keep both live
        if (lane == 0) {
            atomicAdd(&s_pos, pc);
            atomicAdd(&s_psum, (double)ps);
        }
    }

    // Load this row's ce_neg values into registers (L2-resident scratch).
    float    ce[PER];
    unsigned bits[PER];
    #pragma unroll
    for (int i = 0; i < PER; i++) {
        const int a = tid + i * NTB;
        ce[i] = (a < AA) ? g_ce[(size_t)b * AA + a] : 0.f;
        bits[i] = __float_as_uint(ce[i]);
    }
    __syncthreads();

    const int npos = s_pos;
    const int k = min(3 * npos, AA - npos);

    double negsum = 0.0;
    if (k > 0) {
        unsigned lo = 0u, hi = 0x7F800000u;
        int iter = 0;
        while (lo < hi) {
            const unsigned mid = (lo + hi) >> 1;
            unsigned c = 0;
            #pragma unroll
            for (int i = 0; i < PER; i++) c += (bits[i] > mid) ? 1u : 0u;
            c = __reduce_add_sync(0xFFFFFFFFu, c);
            if (lane == 0) atomicAdd(&s_cnt[iter], c);
            __syncthreads();
            const unsigned tot = s_cnt[iter];
            if (tot < (unsigned)k) hi = mid; else lo = mid + 1u;
            iter++;
        }
        // lo = k-th largest value's bit pattern
        const unsigned vbits = lo;
        const float    vth   = __uint_as_float(vbits);

        float    fs  = 0.f;
        unsigned cgt = 0u;
        #pragma unroll
        for (int i = 0; i < PER; i++)
            if (bits[i] > vbits) { fs += ce[i]; cgt++; }
        cgt = __reduce_add_sync(0xFFFFFFFFu, cgt);
        #pragma unroll
        for (int off = 16; off; off >>= 1)
            fs += __shfl_down_sync(0xFFFFFFFFu, fs, off);
        if (lane == 0) {
            atomicAdd(&s_fsum, fs);
            atomicAdd(&s_cgt, cgt);
        }
        __syncthreads();
        negsum = (double)s_fsum + (double)(k - (int)s_cgt) * (double)vth;
    }

    if (tid == 0) {
        g_rowsum[b] = s_psum + negsum;
        g_rowpos[b] = npos;
    }
}

// ---------------------------------------------------------------- Finalize
__global__ void mbl_fin(float* __restrict__ out)
{
    const int tid = threadIdx.x;      // 128 threads
    const unsigned lane = tid & 31u;
    __shared__ double s_s[4];
    __shared__ int    s_p[4];

    double rs = g_rowsum[tid];
    int    rp = g_rowpos[tid];
    #pragma unroll
    for (int off = 16; off; off >>= 1) {
        rs += __shfl_down_sync(0xFFFFFFFFu, rs, off);
        rp += __shfl_down_sync(0xFFFFFFFFu, rp, off);
    }
    if (lane == 0) { s_s[tid >> 5] = rs; s_p[tid >> 5] = rp; }
    __syncthreads();
    if (tid == 0) {
        double tot = s_s[0] + s_s[1] + s_s[2] + s_s[3];
        int    np  = s_p[0] + s_p[1] + s_p[2] + s_p[3];
        out[0] = (float)(tot / (double)np);
    }
}

extern "C" void kernel_launch(void* const* d_in, const int* in_sizes, int n_in,
                              void* d_out, int out_size)
{
    const float* conf = (const float*)d_in[0];
    const float* loc  = (const float*)d_in[1];
    const int*   lab  = (const int*)  d_in[2];
    const float* gloc = (const float*)d_in[3];
    float* out = (float*)d_out;

    mbl_phaseA<<<BLKA, 256>>>(conf, loc, lab, gloc);
    mbl_phaseB<<<ROWS, NTB>>>();
    mbl_fin<<<1, 128>>>(out);
}

// round 5
// speedup vs baseline: 1.9602x; 1.1664x over previous
#include <cuda_runtime.h>
#include <cuda_bf16.h>

// MultiBoxLoss (SSD). 2-kernel pipeline:
//  A) stream: per-anchor CE -> g_ce scratch; per-chunk (32 anchors) positive
//     count + (posCE + smoothL1) partials. Coalesced float4 smem staging with
//     front-batched LDGs (__ldcs). Block 0 zeroes the global accumulators.
//  B) per-row: reduce chunk partials -> k = min(3*npos, nneg); exact k-th
//     largest CE via 3-level radix histogram on float bit patterns
//     (ce_neg >= 0 -> uint-monotone); sum top-k; last block finalizes output.

#define ROWS 128
#define AA   8732
#define CC   21
#define CPR  273            // chunks per row: 272 full (32) + 1 partial (28)
#define TOTCH (ROWS * CPR)  // 34944
#define WPB  8              // warps per block in phase A
#define BLKA (TOTCH / WPB)  // 4368
#define NTB  1024
#define PER  9              // ceil(8732/1024)

__device__ float  g_ce[ROWS * AA];      // ce_neg (0 for positives)
__device__ int    g_chunk_pos[TOTCH];
__device__ float  g_chunk_sum[TOTCH];   // posCE + smoothL1 partial per chunk
__device__ double g_sum;
__device__ unsigned long long g_npos;
__device__ unsigned g_done;

// ---------------------------------------------------------------- Phase A
__global__ __launch_bounds__(256) void mbl_phaseA(
    const float* __restrict__ conf,
    const float* __restrict__ loc,
    const int*   __restrict__ lab,
    const float* __restrict__ gloc)
{
    __shared__ float sbuf[WPB * 672];   // 21504 B

    if (blockIdx.x == 0 && threadIdx.x == 0) {
        g_sum = 0.0; g_npos = 0ull; g_done = 0u;
    }

    const int wid  = threadIdx.x >> 5;
    const int lane = threadIdx.x & 31;
    const int chunk = blockIdx.x * WPB + wid;
    const int row = chunk / CPR;
    const int j   = chunk - row * CPR;
    const int na  = (j == CPR - 1) ? (AA - (CPR - 1) * 32) : 32;  // 28 or 32
    const size_t abase = (size_t)row * AA + (size_t)j * 32;
    const size_t idx = abase + (size_t)lane;

    // Issue label load early so it overlaps staging.
    const int lb = (lane < na) ? __ldg(lab + idx) : 0;

    // Stage this chunk's logits: na*21 floats, contiguous & 16B-aligned.
    // Front-batch all LDGs into registers, then store to smem.
    float* sw = sbuf + wid * 672;
    const float4* src = (const float4*)(conf + abase * CC);
    const int n4 = (na * CC) >> 2;  // 168 or 147
    float4 q[6];
    #pragma unroll
    for (int i = 0; i < 6; i++) {
        const int t = lane + 32 * i;
        if (t < n4) q[i] = __ldcs(src + t);
    }
    #pragma unroll
    for (int i = 0; i < 6; i++) {
        const int t = lane + 32 * i;
        if (t < n4) ((float4*)sw)[t] = q[i];
    }
    __syncwarp();

    float cev = 0.f;    // ce_neg
    int   isp = 0;
    float psum = 0.f;   // posCE + smoothL1 contribution
    if (lane < na) {
        float v[CC];
        #pragma unroll
        for (int c = 0; c < CC; c++) v[c] = sw[lane * CC + c];

        float m = v[0];
        #pragma unroll
        for (int c = 1; c < CC; c++) m = fmaxf(m, v[c]);
        float s = 0.f;
        #pragma unroll
        for (int c = 0; c < CC; c++) s += __expf(v[c] - m);

        const float ce = m + __logf(s) - v[lb];

        if (lb > 0) {
            isp = 1;
            psum = ce;
            #pragma unroll
            for (int qd = 0; qd < 4; qd++) {
                const float d  = loc[idx * 4 + qd] - gloc[idx * 4 + qd];
                const float ad = fabsf(d);
                psum += (ad < 1.f) ? 0.5f * d * d : ad - 0.5f;
            }
        } else {
            cev = ce;   // strictly > 0 for finite logits
        }
        g_ce[idx] = cev;
    }

    // Warp-level chunk partials
    int pc = (int)__reduce_add_sync(0xFFFFFFFFu, (unsigned)isp);
    #pragma unroll
    for (int off = 16; off; off >>= 1)
        psum += __shfl_xor_sync(0xFFFFFFFFu, psum, off);
    if (lane == 0) {
        g_chunk_pos[chunk] = pc;
        g_chunk_sum[chunk] = psum;
    }
}

// ---------------------------------------------------------------- Phase B
// warp-0 helper: scan bins descending, find the bin where cumulative count
// reaches rank r; write bin index + rank-within-bin to smem.
__device__ __forceinline__ void find_bin_w0(
    const unsigned* __restrict__ h, int nbins, unsigned r,
    int* selbin, unsigned* selrank, unsigned lane)
{
    unsigned run = 0;
    for (int it = 0; it * 32 < nbins; it++) {
        const int bin = nbins - 1 - (it * 32 + (int)lane);  // lane0 = highest
        unsigned c = (bin >= 0) ? h[bin] : 0u;
        unsigned pre = c;
        #pragma unroll
        for (int off = 1; off < 32; off <<= 1) {
            const unsigned x = __shfl_up_sync(0xFFFFFFFFu, pre, off);
            if (lane >= off) pre += x;
        }
        const unsigned cum = run + pre;
        const unsigned ball = __ballot_sync(0xFFFFFFFFu, cum >= r);
        if (ball) {
            const int l = __ffs((int)ball) - 1;     // first (highest) bin
            const unsigned cum_l = __shfl_sync(0xFFFFFFFFu, cum, l);
            const unsigned c_l   = __shfl_sync(0xFFFFFFFFu, c,   l);
            if (lane == 0) {
                *selbin  = nbins - 1 - (it * 32 + l);
                *selrank = r - (cum_l - c_l);
            }
            return;
        }
        run = __shfl_sync(0xFFFFFFFFu, cum, 31);
    }
    if (lane == 0) { *selbin = 0; *selrank = 1u; }  // unreachable
}

__global__ __launch_bounds__(NTB) void mbl_phaseB(float* __restrict__ out)
{
    const int b    = blockIdx.x;
    const int tid  = threadIdx.x;
    const unsigned lane = tid & 31u;

    __shared__ unsigned s_hist[2048];
    __shared__ int      s_selbin;
    __shared__ unsigned s_selrank;
    __shared__ int      s_pos;
    __shared__ double   s_psum;
    __shared__ float    s_fsum;
    __shared__ unsigned s_cgt;

    if (tid == 0) { s_pos = 0; s_psum = 0.0; s_fsum = 0.f; s_cgt = 0u; }
    __syncthreads();

    // Reduce this row's chunk partials (273 of them).
    {
        int   pc = 0;
        float ps = 0.f;
        if (tid < CPR) {
            pc = g_chunk_pos[b * CPR + tid];
            ps = g_chunk_sum[b * CPR + tid];
        }
        pc = (int)__reduce_add_sync(0xFFFFFFFFu, (unsigned)pc);
        #pragma unroll
        for (int off = 16; off; off >>= 1)
            ps += __shfl_down_sync(0xFFFFFFFFu, ps, off);
        if (lane == 0) {
            atomicAdd(&s_pos, pc);
            atomicAdd(&s_psum, (double)ps);
        }
    }

    // Load this row's ce_neg values into registers (L2-resident scratch).
    float    ce[PER];
    unsigned bits[PER];
    #pragma unroll
    for (int i = 0; i < PER; i++) {
        const int a = tid + i * NTB;
        ce[i] = (a < AA) ? g_ce[(size_t)b * AA + a] : 0.f;
        bits[i] = __float_as_uint(ce[i]);
    }
    __syncthreads();

    const int npos = s_pos;
    const int k = min(3 * npos, AA - npos);

    double negsum = 0.0;
    if (k > 0) {
        unsigned r = (unsigned)k;

        // ---- Level 1: bits[30:21] ----
        s_hist[tid] = 0u;
        __syncthreads();
        #pragma unroll
        for (int i = 0; i < PER; i++)
            atomicAdd(&s_hist[bits[i] >> 21], 1u);
        __syncthreads();
        if (tid < 32) find_bin_w0(s_hist, 1024, r, &s_selbin, &s_selrank, lane);
        __syncthreads();
        const unsigned B1 = (unsigned)s_selbin;
        r = s_selrank;
        __syncthreads();

        // ---- Level 2: bits[20:11] among bin1 == B1 ----
        s_hist[tid] = 0u;
        __syncthreads();
        #pragma unroll
        for (int i = 0; i < PER; i++)
            if ((bits[i] >> 21) == B1)
                atomicAdd(&s_hist[(bits[i] >> 11) & 1023u], 1u);
        __syncthreads();
        if (tid < 32) find_bin_w0(s_hist, 1024, r, &s_selbin, &s_selrank, lane);
        __syncthreads();
        const unsigned top21 = (B1 << 10) | (unsigned)s_selbin;
        r = s_selrank;
        __syncthreads();

        // ---- Level 3: bits[10:0] among top21 match ----
        s_hist[tid] = 0u;
        s_hist[tid + 1024] = 0u;
        __syncthreads();
        #pragma unroll
        for (int i = 0; i < PER; i++)
            if ((bits[i] >> 11) == top21)
                atomicAdd(&s_hist[bits[i] & 2047u], 1u);
        __syncthreads();
        if (tid < 32) find_bin_w0(s_hist, 2048, r, &s_selbin, &s_selrank, lane);
        __syncthreads();

        const unsigned vbits = (top21 << 11) | (unsigned)s_selbin;
        const float    vth   = __uint_as_float(vbits);

        // sum of values strictly greater + tie fill at threshold
        float    fs  = 0.f;
        unsigned cgt = 0u;
        #pragma unroll
        for (int i = 0; i < PER; i++)
            if (bits[i] > vbits) { fs += ce[i]; cgt++; }
        cgt = __reduce_add_sync(0xFFFFFFFFu, cgt);
        #pragma unroll
        for (int off = 16; off; off >>= 1)
            fs += __shfl_down_sync(0xFFFFFFFFu, fs, off);
        if (lane == 0) {
            atomicAdd(&s_fsum, fs);
            atomicAdd(&s_cgt, cgt);
        }
        __syncthreads();
        negsum = (double)s_fsum + (double)(k - (int)s_cgt) * (double)vth;
    }

    if (tid == 0) {
        atomicAdd(&g_sum, s_psum + negsum);
        atomicAdd(&g_npos, (unsigned long long)npos);
        __threadfence();
        const unsigned done = atomicAdd(&g_done, 1u);
        if (done == ROWS - 1) {
            __threadfence();
            const double ts = atomicAdd(&g_sum, 0.0);
            const unsigned long long tp = atomicAdd(&g_npos, 0ull);
            out[0] = (float)(ts / (double)tp);
        }
    }
}

extern "C" void kernel_launch(void* const* d_in, const int* in_sizes, int n_in,
                              void* d_out, int out_size)
{
    const float* conf = (const float*)d_in[0];
    const float* loc  = (const float*)d_in[1];
    const int*   lab  = (const int*)  d_in[2];
    const float* gloc = (const float*)d_in[3];
    float* out = (float*)d_out;

    mbl_phaseA<<<BLKA, 256>>>(conf, loc, lab, gloc);
    mbl_phaseB<<<ROWS, NTB>>>(out);
}